// round 15
// baseline (speedup 1.0000x reference)
#include <cuda_runtime.h>
#include <math.h>
#include <stdint.h>

// Problem dims
#define Bn   64
#define Ln   49
#define Tn   20
#define Vn   10000
#define En   512
#define ENCn 2048
#define Dn   512
#define An   512
#define XKn  (En + ENCn)        // 2560
#define KTOT (XKn + Dn)         // 3072

// packed-operand geometry
#define KB_G   (KTOT / 8)       // 384  (gates K blocks)
#define KB_L   (Dn / 8)         // 64   (logits / dec K blocks)
#define KB_E   (ENCn / 8)       // 256  (enc K blocks)
#define MF_ENC ((Bn * Ln) / 16) // 196
#define NT_OUT 157              // ceil(10000/64)
#define NT_G   (4 * Dn / 64)    // 32
#define NT_A   (An / 64)        // 8
#define GSPLIT 16               // gates split-K
#define NKB_G  (KB_G / GSPLIT)  // 24

// A-pack plane strides (in 32-bit words): MF * KB * 128
#define XPLANE (4 * KB_G * 128)        // x  (64 x 3072)
#define HPLANE (4 * KB_L * 128)        // h  (64 x 512)
#define TPLANE (Tn * HPLANE)           // all-steps h
#define EPLANE (MF_ENC * KB_E * 128)   // enc (3136 x 2048)
#define MPLANE (4 * KB_E * 128)        // mean (64 x 2048)

// ----- scratch (__device__ globals; no allocations allowed) -----
__device__ float    g_mean [Bn * ENCn];
__device__ float    g_h    [Bn * Dn];
__device__ float    g_c    [Bn * Dn];
__device__ float    g_encp [Bn * Ln * An];
__device__ float    g_decp [Bn * An];
__device__ float    g_gpart[GSPLIT][Bn * 4 * Dn];

__device__ uint32_t g_xpk     [2 * XPLANE];
__device__ uint32_t g_hpk     [2 * HPLANE];    // h_init pack (initial dec_proj)
__device__ uint32_t g_hall    [2 * TPLANE];    // packed h for every step
__device__ uint32_t g_apk_enc [2 * EPLANE];
__device__ uint32_t g_apk_mean[2 * MPLANE];

__device__ uint32_t g_bpk_out [NT_OUT * KB_L * 1024];
__device__ uint32_t g_bpk_g   [NT_G   * KB_G * 1024];
__device__ uint32_t g_bpk_ea  [NT_A   * KB_E * 1024];
__device__ uint32_t g_bpk_ih  [NT_A   * KB_E * 1024];
__device__ uint32_t g_bpk_ic  [NT_A   * KB_E * 1024];
__device__ uint32_t g_bpk_da  [NT_A   * KB_L * 1024];

// ============================================================
// tf32 helpers
// ============================================================
__device__ __forceinline__ void split_tf32(float v, uint32_t& hi, uint32_t& lo) {
    uint32_t h;
    asm("cvt.rna.tf32.f32 %0, %1;" : "=r"(h) : "f"(v));
    float hf = __uint_as_float(h);
    float r  = v - hf;
    uint32_t l;
    asm("cvt.rna.tf32.f32 %0, %1;" : "=r"(l) : "f"(r));
    hi = h; lo = l;
}

__device__ __forceinline__ void mma_tf32(float c[4], const uint32_t a[4], const uint32_t b[2]) {
    asm volatile(
        "mma.sync.aligned.m16n8k8.row.col.f32.tf32.tf32.f32 "
        "{%0,%1,%2,%3}, {%4,%5,%6,%7}, {%8,%9}, {%0,%1,%2,%3};\n"
        : "+f"(c[0]), "+f"(c[1]), "+f"(c[2]), "+f"(c[3])
        : "r"(a[0]), "r"(a[1]), "r"(a[2]), "r"(a[3]),
          "r"(b[0]), "r"(b[1]));
}

__device__ __forceinline__ void mma3(float c[4], const uint4& ah, const uint4& al, const uint4& bb) {
    uint32_t a_h[4] = {ah.x, ah.y, ah.z, ah.w};
    uint32_t a_l[4] = {al.x, al.y, al.z, al.w};
    uint32_t b_h[2] = {bb.x, bb.y};
    uint32_t b_l[2] = {bb.z, bb.w};
    mma_tf32(c, a_h, b_l);
    mma_tf32(c, a_l, b_h);
    mma_tf32(c, a_h, b_h);
}

// ============================================================
// core packed 64x64 tile with register prefetch (software pipeline)
// ============================================================
__device__ __forceinline__ void gemm_tile(
    const uint32_t* __restrict__ Apk, int aplane, int kbtot, int kb0, int nkb,
    const uint32_t* __restrict__ Bpk, int btile_base,  // = ntile*kbtot + kb0
    int mf0, int lane, int wm, int wn, float acc[2][2][4])
{
    const uint4* aH[2];
    const uint4* aL[2];
    #pragma unroll
    for (int i = 0; i < 2; i++) {
        int mf = mf0 + wm * 2 + i;
        const uint32_t* p = Apk + ((size_t)(mf * kbtot + kb0) * 32 + lane) * 4;
        aH[i] = (const uint4*)p;
        aL[i] = (const uint4*)(p + aplane);
    }
    const uint4* bP[2];
    #pragma unroll
    for (int j = 0; j < 2; j++) {
        int nf = wn * 2 + j;
        bP[j] = (const uint4*)(Bpk + (((size_t)btile_base * 8 + nf) * 32 + lane) * 4);
    }

    uint4 ah0 = aH[0][0], al0 = aL[0][0];
    uint4 ah1 = aH[1][0], al1 = aL[1][0];
    uint4 b0  = bP[0][0], b1  = bP[1][0];

    for (int kb = 1; kb < nkb; kb++) {
        uint4 nah0 = aH[0][(size_t)kb * 32];
        uint4 nal0 = aL[0][(size_t)kb * 32];
        uint4 nah1 = aH[1][(size_t)kb * 32];
        uint4 nal1 = aL[1][(size_t)kb * 32];
        uint4 nb0  = bP[0][(size_t)kb * 256];
        uint4 nb1  = bP[1][(size_t)kb * 256];
        mma3(acc[0][0], ah0, al0, b0);
        mma3(acc[0][1], ah0, al0, b1);
        mma3(acc[1][0], ah1, al1, b0);
        mma3(acc[1][1], ah1, al1, b1);
        ah0 = nah0; al0 = nal0; ah1 = nah1; al1 = nal1; b0 = nb0; b1 = nb1;
    }
    mma3(acc[0][0], ah0, al0, b0);
    mma3(acc[0][1], ah0, al0, b1);
    mma3(acc[1][0], ah1, al1, b0);
    mma3(acc[1][1], ah1, al1, b1);
}

// ============================================================
// generic packed GEMM. grid=(ntiles, mtiles, ksplit)
// ============================================================
__global__ __launch_bounds__(256)
void gemm_pk(const uint32_t* __restrict__ Apk, int aplane, int kbtot,
             const uint32_t* __restrict__ Bpk,
             const float* __restrict__ bias, float* __restrict__ Cp,
             int nkb, int ldc, int N, long long pstride)
{
    const int tid = threadIdx.x, lane = tid & 31, warp = tid >> 5;
    const int wm = warp >> 2, wn = warp & 3;
    const int gid = lane >> 2, tig = lane & 3;
    const int ntile = blockIdx.x, mtile = blockIdx.y, z = blockIdx.z;
    const int kb0 = z * nkb;
    Cp += (long long)z * pstride;

    float acc[2][2][4] = {};
    gemm_tile(Apk, aplane, kbtot, kb0, nkb, Bpk, ntile * kbtot + kb0,
              mtile * 4, lane, wm, wn, acc);

    #pragma unroll
    for (int i = 0; i < 2; i++)
        #pragma unroll
        for (int j = 0; j < 2; j++)
            #pragma unroll
            for (int r = 0; r < 4; r++) {
                int gm = mtile * 64 + wm * 32 + i * 16 + gid + ((r >> 1) & 1) * 8;
                int gn = ntile * 64 + wn * 16 + j * 8 + tig * 2 + (r & 1);
                if (gn < N) {
                    float v = acc[i][j][r];
                    if (bias) v += bias[gn];
                    Cp[(long long)gm * ldc + gn] = v;
                }
            }
}

// ============================================================
// dec_proj GEMM for step t+1: reads h from g_hall plane t
// grid = (NT_A, 1, 1)
// ============================================================
__global__ __launch_bounds__(256)
void dec_gemm(int t, const float* __restrict__ b_dec)
{
    const int tid = threadIdx.x, lane = tid & 31, warp = tid >> 5;
    const int wm = warp >> 2, wn = warp & 3;
    const int gid = lane >> 2, tig = lane & 3;
    const int ntile = blockIdx.x;

    float acc[2][2][4] = {};
    gemm_tile(g_hall, TPLANE, KB_L, 0, KB_L, g_bpk_da,
              ntile * KB_L, t * 4, lane, wm, wn, acc);

    #pragma unroll
    for (int i = 0; i < 2; i++)
        #pragma unroll
        for (int j = 0; j < 2; j++)
            #pragma unroll
            for (int r = 0; r < 4; r++) {
                int gm = wm * 32 + i * 16 + gid + ((r >> 1) & 1) * 8;
                int gn = ntile * 64 + wn * 16 + j * 8 + tig * 2 + (r & 1);
                g_decp[gm * An + gn] = acc[i][j][r] + b_dec[gn];
            }
}

// ============================================================
// batched logits GEMM over ALL steps: grid=(NT_OUT, Tn, 1)
// out[(b*Tn + t)*Vn + v] = h_t[b] @ W_out + b_out
// ============================================================
__global__ __launch_bounds__(256)
void logits_all(const float* __restrict__ bias, float* __restrict__ outp)
{
    const int tid = threadIdx.x, lane = tid & 31, warp = tid >> 5;
    const int wm = warp >> 2, wn = warp & 3;
    const int gid = lane >> 2, tig = lane & 3;
    const int ntile = blockIdx.x, t = blockIdx.y;

    float acc[2][2][4] = {};
    gemm_tile(g_hall, TPLANE, KB_L, 0, KB_L, g_bpk_out,
              ntile * KB_L, t * 4, lane, wm, wn, acc);

    #pragma unroll
    for (int i = 0; i < 2; i++)
        #pragma unroll
        for (int j = 0; j < 2; j++)
            #pragma unroll
            for (int r = 0; r < 4; r++) {
                int b  = wm * 32 + i * 16 + gid + ((r >> 1) & 1) * 8;
                int gn = ntile * 64 + wn * 16 + j * 8 + tig * 2 + (r & 1);
                if (gn < Vn)
                    outp[((size_t)b * Tn + t) * Vn + gn] = acc[i][j][r] + bias[gn];
            }
}

// ============================================================
// mean over L of encoder_out -> g_mean (B, ENC)
// ============================================================
__global__ void mean_kernel(const float* __restrict__ enc) {
    int idx = blockIdx.x * blockDim.x + threadIdx.x;
    if (idx >= Bn * ENCn) return;
    int b = idx / ENCn, e = idx % ENCn;
    float s = 0.f;
    #pragma unroll 7
    for (int l = 0; l < Ln; l++) s += enc[(b * Ln + l) * ENCn + e];
    g_mean[idx] = s * (1.0f / (float)Ln);
}

// ============================================================
// pack A (row-major M x Kld fp32) into fragment order (hi/lo planes)
// ============================================================
__global__ void pack_A_plain(const float* __restrict__ A, uint32_t* __restrict__ out,
                             int plane, int KBtot, int Kld, int total)
{
    int id = blockIdx.x * 256 + threadIdx.x;
    if (id >= total) return;
    int lane = id & 31;
    int kb   = (id >> 5) % KBtot;
    int mf   = (id >> 5) / KBtot;
    int gid = lane >> 2, tig = lane & 3;
    long long m0 = mf * 16 + gid;
    int k0 = kb * 8 + tig;
    float v0 = A[m0 * Kld + k0];
    float v1 = A[(m0 + 8) * Kld + k0];
    float v2 = A[m0 * Kld + k0 + 4];
    float v3 = A[(m0 + 8) * Kld + k0 + 4];
    uint4 H, L;
    split_tf32(v0, H.x, L.x); split_tf32(v1, H.y, L.y);
    split_tf32(v2, H.z, L.z); split_tf32(v3, H.w, L.w);
    ((uint4*)out)[id] = H;
    ((uint4*)(out + plane))[id] = L;
}

// ============================================================
// pack B (row-major K x N fp32, ld=ldb) into fragment order
// ============================================================
__global__ void pack_B_kn(const float* __restrict__ B, uint32_t* __restrict__ out,
                          int KBtot, int N, int ldb, int total)
{
    int id = blockIdx.x * 256 + threadIdx.x;
    if (id >= total) return;
    int lane = id & 31;
    int rest = id >> 5;
    int nf = rest & 7; rest >>= 3;
    int kb = rest % KBtot;
    int ntile = rest / KBtot;
    int gid = lane >> 2, tig = lane & 3;
    int n = ntile * 64 + nf * 8 + gid;
    long long k = kb * 8 + tig;
    float v0 = (n < N) ? B[k * ldb + n] : 0.f;
    float v1 = (n < N) ? B[(k + 4) * ldb + n] : 0.f;
    uint4 W;
    split_tf32(v0, W.x, W.z);
    split_tf32(v1, W.y, W.w);
    ((uint4*)out)[id] = W;
}

// ============================================================
// pack gates B: B[k][n] = k<XKn ? W_ih[n][k] : W_hh[n][k-XKn]
// ============================================================
__global__ void pack_B_gates(const float* __restrict__ Wih, const float* __restrict__ Whh,
                             uint32_t* __restrict__ out, int total)
{
    int id = blockIdx.x * 256 + threadIdx.x;
    if (id >= total) return;
    int lane = id & 31;
    int rest = id >> 5;
    int nf = rest & 7; rest >>= 3;
    int kb = rest % KB_G;
    int ntile = rest / KB_G;
    int gid = lane >> 2, tig = lane & 3;
    long long n = ntile * 64 + nf * 8 + gid;
    int k = kb * 8 + tig;
    float v0 = (k < XKn)     ? Wih[n * XKn + k]     : Whh[n * Dn + (k - XKn)];
    float v1 = (k + 4 < XKn) ? Wih[n * XKn + k + 4] : Whh[n * Dn + (k + 4 - XKn)];
    uint4 W;
    split_tf32(v0, W.x, W.z);
    split_tf32(v1, W.y, W.w);
    ((uint4*)out)[id] = W;
}

// ============================================================
// attention (512 threads): scores, softmax, context, x-pack
// dec_proj precomputed into g_decp
// ============================================================
__global__ __launch_bounds__(512)
void attention_kernel(int t, const float* __restrict__ enc,
                      const float* __restrict__ wf,
                      const float* __restrict__ bf,
                      const int* __restrict__ captions,
                      const float* __restrict__ emb,
                      float* __restrict__ alphas_out)
{
    const int b   = blockIdx.x;
    const int tid = threadIdx.x;
    const int lane = tid & 31, wid = tid >> 5;   // 16 warps

    __shared__ float sh  [Dn];
    __shared__ float swf [An];
    __shared__ float sdec[An];
    __shared__ float ssc [Ln];
    __shared__ float sal [Ln];
    __shared__ float sctx[ENCn];

    for (int i = tid; i < Dn; i += 512) sh[i]   = g_h[b * Dn + i];
    for (int i = tid; i < An; i += 512) swf[i]  = wf[i];
    for (int i = tid; i < An; i += 512) sdec[i] = g_decp[b * An + i];
    __syncthreads();

    // scores: one warp per l
    for (int l = wid; l < Ln; l += 16) {
        const float* ep = &g_encp[(b * Ln + l) * An];
        float s = 0.f;
        #pragma unroll 4
        for (int a = lane; a < An; a += 32) {
            float v = ep[a] + sdec[a];
            v = fmaxf(v, 0.f);
            s += v * swf[a];
        }
        #pragma unroll
        for (int off = 16; off > 0; off >>= 1)
            s += __shfl_xor_sync(0xFFFFFFFFu, s, off);
        if (lane == 0) ssc[l] = s + bf[0];
    }
    __syncthreads();

    // softmax (warp 0)
    if (tid < 32) {
        float v0 = ssc[lane];
        float v1 = (lane + 32 < Ln) ? ssc[lane + 32] : -1e30f;
        float mx = fmaxf(v0, v1);
        #pragma unroll
        for (int off = 16; off > 0; off >>= 1)
            mx = fmaxf(mx, __shfl_xor_sync(0xFFFFFFFFu, mx, off));
        float e0 = expf(v0 - mx);
        float e1 = (lane + 32 < Ln) ? expf(v1 - mx) : 0.f;
        float s = e0 + e1;
        #pragma unroll
        for (int off = 16; off > 0; off >>= 1)
            s += __shfl_xor_sync(0xFFFFFFFFu, s, off);
        float inv = 1.0f / s;
        sal[lane] = e0 * inv;
        if (lane + 32 < Ln) sal[lane + 32] = e1 * inv;
    }
    __syncthreads();

    if (tid < Ln) alphas_out[(b * Tn + t) * Ln + tid] = sal[tid];

    // context
    for (int e = tid; e < ENCn; e += 512) {
        float acc = 0.f;
        #pragma unroll 7
        for (int l = 0; l < Ln; l++)
            acc += sal[l] * enc[(b * Ln + l) * ENCn + e];
        sctx[e] = acc;
    }
    __syncthreads();

    // pack x = [emb | ctx | h] row b into fragment layout
    {
        const int cap = captions[b * Tn + t];
        const int r = b & 15, mf = b >> 4;
        for (int k = tid; k < KTOT; k += 512) {
            float v = (k < En) ? emb[cap * En + k]
                    : (k < XKn) ? sctx[k - En]
                                : sh[k - XKn];
            uint32_t hi, lo; split_tf32(v, hi, lo);
            int kb = k >> 3;
            int ln2 = ((r & 7) << 2) | (k & 3);
            int w = ((r >> 3) & 1) + ((k & 4) ? 2 : 0);
            int idx = ((mf * KB_G + kb) * 32 + ln2) * 4 + w;
            g_xpk[idx] = hi;
            g_xpk[XPLANE + idx] = lo;
        }
    }
}

// ============================================================
// LSTM pointwise + pack h into this step's plane of g_hall
// ============================================================
__global__ __launch_bounds__(256)
void lstm_pointwise(int t, const float* __restrict__ b_ih, const float* __restrict__ b_hh)
{
    int idx = blockIdx.x * blockDim.x + threadIdx.x;
    if (idx >= Bn * Dn) return;
    int b = idx / Dn, d = idx % Dn;
    int base = b * 4 * Dn;

    float gi = b_ih[d]          + b_hh[d];
    float gf = b_ih[Dn + d]     + b_hh[Dn + d];
    float gg = b_ih[2 * Dn + d] + b_hh[2 * Dn + d];
    float go = b_ih[3 * Dn + d] + b_hh[3 * Dn + d];
    #pragma unroll
    for (int z = 0; z < GSPLIT; z++) {
        gi += g_gpart[z][base + d];
        gf += g_gpart[z][base + Dn + d];
        gg += g_gpart[z][base + 2 * Dn + d];
        go += g_gpart[z][base + 3 * Dn + d];
    }
    float i = 1.0f / (1.0f + expf(-gi));
    float f = 1.0f / (1.0f + expf(-gf));
    float g = tanhf(gg);
    float o = 1.0f / (1.0f + expf(-go));
    float c = f * g_c[idx] + i * g;
    g_c[idx] = c;
    float h = o * tanhf(c);
    g_h[idx] = h;

    // pack into g_hall plane for step t (mf_global = t*4 + b/16)
    uint32_t hi, lo; split_tf32(h, hi, lo);
    int r = b & 15, mfg = t * 4 + (b >> 4);
    int kb = d >> 3;
    int ln2 = ((r & 7) << 2) | (d & 3);
    int w = ((r >> 3) & 1) + ((d & 4) ? 2 : 0);
    int j = ((mfg * KB_L + kb) * 32 + ln2) * 4 + w;
    g_hall[j] = hi;
    g_hall[TPLANE + j] = lo;
}

// ============================================================
// launch
// ============================================================
extern "C" void kernel_launch(void* const* d_in, const int* in_sizes, int n_in,
                              void* d_out, int out_size)
{
    const float* enc       = (const float*)d_in[0];
    const int*   captions  = (const int*)  d_in[1];
    const float* emb       = (const float*)d_in[2];
    const float* W_enc_att = (const float*)d_in[3];
    const float* b_enc_att = (const float*)d_in[4];
    const float* W_dec_att = (const float*)d_in[5];
    const float* b_dec_att = (const float*)d_in[6];
    const float* w_full    = (const float*)d_in[7];
    const float* b_full    = (const float*)d_in[8];
    const float* W_ih      = (const float*)d_in[9];
    const float* b_ih      = (const float*)d_in[10];
    const float* W_hh      = (const float*)d_in[11];
    const float* b_hh      = (const float*)d_in[12];
    const float* W_init_h  = (const float*)d_in[13];
    const float* b_init_h  = (const float*)d_in[14];
    const float* W_init_c  = (const float*)d_in[15];
    const float* b_init_c  = (const float*)d_in[16];
    const float* W_out     = (const float*)d_in[17];
    const float* b_out     = (const float*)d_in[18];

    float* out        = (float*)d_out;
    float* alphas_out = out + (size_t)Bn * Tn * Vn;

    float *p_mean, *p_h, *p_c, *p_encp, *p_gpart, *p_decp;
    uint32_t *p_xpk, *p_hpk, *p_apk_enc, *p_apk_mean;
    uint32_t *p_bout, *p_bg, *p_bea, *p_bih, *p_bic, *p_bda;
    cudaGetSymbolAddress((void**)&p_mean,     g_mean);
    cudaGetSymbolAddress((void**)&p_h,        g_h);
    cudaGetSymbolAddress((void**)&p_c,        g_c);
    cudaGetSymbolAddress((void**)&p_encp,     g_encp);
    cudaGetSymbolAddress((void**)&p_decp,     g_decp);
    cudaGetSymbolAddress((void**)&p_gpart,    g_gpart);
    cudaGetSymbolAddress((void**)&p_xpk,      g_xpk);
    cudaGetSymbolAddress((void**)&p_hpk,      g_hpk);
    cudaGetSymbolAddress((void**)&p_apk_enc,  g_apk_enc);
    cudaGetSymbolAddress((void**)&p_apk_mean, g_apk_mean);
    cudaGetSymbolAddress((void**)&p_bout,     g_bpk_out);
    cudaGetSymbolAddress((void**)&p_bg,       g_bpk_g);
    cudaGetSymbolAddress((void**)&p_bea,      g_bpk_ea);
    cudaGetSymbolAddress((void**)&p_bih,      g_bpk_ih);
    cudaGetSymbolAddress((void**)&p_bic,      g_bpk_ic);
    cudaGetSymbolAddress((void**)&p_bda,      g_bpk_da);

    // ---- weight packs ----
    {
        int tot = NT_OUT * KB_L * 8 * 32;
        pack_B_kn<<<(tot + 255) / 256, 256>>>(W_out, p_bout, KB_L, Vn, Vn, tot);
    }
    {
        int tot = NT_G * KB_G * 8 * 32;
        pack_B_gates<<<(tot + 255) / 256, 256>>>(W_ih, W_hh, p_bg, tot);
    }
    {
        int tot = NT_A * KB_E * 8 * 32;
        pack_B_kn<<<(tot + 255) / 256, 256>>>(W_enc_att, p_bea, KB_E, An, An, tot);
        pack_B_kn<<<(tot + 255) / 256, 256>>>(W_init_h,  p_bih, KB_E, Dn, Dn, tot);
        pack_B_kn<<<(tot + 255) / 256, 256>>>(W_init_c,  p_bic, KB_E, Dn, Dn, tot);
    }
    {
        int tot = NT_A * KB_L * 8 * 32;
        pack_B_kn<<<(tot + 255) / 256, 256>>>(W_dec_att, p_bda, KB_L, An, An, tot);
    }

    // ---- init ----
    mean_kernel<<<(Bn * ENCn + 255) / 256, 256>>>(enc);
    {
        int tot = 4 * KB_E * 32;
        pack_A_plain<<<(tot + 255) / 256, 256>>>(p_mean, p_apk_mean, MPLANE, KB_E, ENCn, tot);
    }
    gemm_pk<<<dim3(NT_A, 1, 1), 256>>>(p_apk_mean, MPLANE, KB_E, p_bih,
                                       b_init_h, p_h, KB_E, Dn, Dn, 0);
    gemm_pk<<<dim3(NT_A, 1, 1), 256>>>(p_apk_mean, MPLANE, KB_E, p_bic,
                                       b_init_c, p_c, KB_E, Dn, Dn, 0);
    {
        int tot = MF_ENC * KB_E * 32;
        pack_A_plain<<<(tot + 255) / 256, 256>>>(enc, p_apk_enc, EPLANE, KB_E, ENCn, tot);
    }
    gemm_pk<<<dim3(NT_A, Bn * Ln / 64, 1), 256>>>(p_apk_enc, EPLANE, KB_E, p_bea,
                                                  b_enc_att, p_encp, KB_E, An, An, 0);
    // pack h_init and compute initial dec_proj
    {
        int tot = 4 * KB_L * 32;
        pack_A_plain<<<(tot + 255) / 256, 256>>>(p_h, p_hpk, HPLANE, KB_L, Dn, tot);
    }
    gemm_pk<<<dim3(NT_A, 1, 1), 256>>>(p_hpk, HPLANE, KB_L, p_bda,
                                       b_dec_att, p_decp, KB_L, An, An, 0);

    // ---- time steps (4 kernels each; logits deferred) ----
    for (int t = 0; t < Tn; t++) {
        attention_kernel<<<Bn, 512>>>(t, enc, w_full, b_full,
                                      captions, emb, alphas_out);
        gemm_pk<<<dim3(NT_G, 1, GSPLIT), 256>>>(p_xpk, XPLANE, KB_G, p_bg,
                                                nullptr, p_gpart,
                                                NKB_G, 4 * Dn, 4 * Dn,
                                                (long long)Bn * 4 * Dn);
        lstm_pointwise<<<(Bn * Dn + 255) / 256, 256>>>(t, b_ih, b_hh);
        if (t + 1 < Tn)
            dec_gemm<<<NT_A, 256>>>(t, b_dec_att);
    }

    // ---- batched logits for all steps (full-chip GEMM) ----
    logits_all<<<dim3(NT_OUT, Tn, 1), 256>>>(b_out, out);
}

// round 16
// speedup vs baseline: 1.0050x; 1.0050x over previous
#include <cuda_runtime.h>
#include <math.h>
#include <stdint.h>

// Problem dims
#define Bn   64
#define Ln   49
#define Tn   20
#define Vn   10000
#define En   512
#define ENCn 2048
#define Dn   512
#define An   512
#define XKn  (En + ENCn)        // 2560
#define KTOT (XKn + Dn)         // 3072

// packed-operand geometry
#define KB_G   (KTOT / 8)       // 384  (gates K blocks)
#define KB_L   (Dn / 8)         // 64   (logits / dec K blocks)
#define KB_E   (ENCn / 8)       // 256  (enc K blocks)
#define MF_ENC ((Bn * Ln) / 16) // 196
#define NT_OUT 157              // ceil(10000/64)
#define NT_G   (4 * Dn / 64)    // 32
#define NT_A   (An / 64)        // 8
#define GSPLIT 16               // gates split-K
#define NKB_G  (KB_G / GSPLIT)  // 24

// A-pack plane strides (in 32-bit words): MF * KB * 128
#define XPLANE (4 * KB_G * 128)        // x  (64 x 3072)
#define HPLANE (4 * KB_L * 128)        // h  (64 x 512)
#define TPLANE (Tn * HPLANE)           // all-steps h
#define EPLANE (MF_ENC * KB_E * 128)   // enc (3136 x 2048)
#define MPLANE (4 * KB_E * 128)        // mean (64 x 2048)

// ----- scratch (__device__ globals; no allocations allowed) -----
__device__ float    g_mean [Bn * ENCn];
__device__ float    g_h    [Bn * Dn];
__device__ float    g_c    [Bn * Dn];
__device__ float    g_encp [Bn * Ln * An];
__device__ float    g_decp [Bn * An];
__device__ float    g_gpart[GSPLIT][Bn * 4 * Dn];

__device__ uint32_t g_xpk     [2 * XPLANE];
__device__ uint32_t g_hpk     [2 * HPLANE];    // h_init pack (initial dec_proj)
__device__ uint32_t g_hall    [2 * TPLANE];    // packed h for every step
__device__ uint32_t g_apk_enc [2 * EPLANE];
__device__ uint32_t g_apk_mean[2 * MPLANE];

__device__ uint32_t g_bpk_out [NT_OUT * KB_L * 1024];
__device__ uint32_t g_bpk_g   [NT_G   * KB_G * 1024];
__device__ uint32_t g_bpk_ea  [NT_A   * KB_E * 1024];
__device__ uint32_t g_bpk_ih  [NT_A   * KB_E * 1024];
__device__ uint32_t g_bpk_ic  [NT_A   * KB_E * 1024];
__device__ uint32_t g_bpk_da  [NT_A   * KB_L * 1024];

// ============================================================
// tf32 helpers
// ============================================================
__device__ __forceinline__ void split_tf32(float v, uint32_t& hi, uint32_t& lo) {
    uint32_t h;
    asm("cvt.rna.tf32.f32 %0, %1;" : "=r"(h) : "f"(v));
    float hf = __uint_as_float(h);
    float r  = v - hf;
    uint32_t l;
    asm("cvt.rna.tf32.f32 %0, %1;" : "=r"(l) : "f"(r));
    hi = h; lo = l;
}

__device__ __forceinline__ void mma_tf32(float c[4], const uint32_t a[4], const uint32_t b[2]) {
    asm volatile(
        "mma.sync.aligned.m16n8k8.row.col.f32.tf32.tf32.f32 "
        "{%0,%1,%2,%3}, {%4,%5,%6,%7}, {%8,%9}, {%0,%1,%2,%3};\n"
        : "+f"(c[0]), "+f"(c[1]), "+f"(c[2]), "+f"(c[3])
        : "r"(a[0]), "r"(a[1]), "r"(a[2]), "r"(a[3]),
          "r"(b[0]), "r"(b[1]));
}

__device__ __forceinline__ void mma3(float c[4], const uint4& ah, const uint4& al, const uint4& bb) {
    uint32_t a_h[4] = {ah.x, ah.y, ah.z, ah.w};
    uint32_t a_l[4] = {al.x, al.y, al.z, al.w};
    uint32_t b_h[2] = {bb.x, bb.y};
    uint32_t b_l[2] = {bb.z, bb.w};
    mma_tf32(c, a_h, b_l);
    mma_tf32(c, a_l, b_h);
    mma_tf32(c, a_h, b_h);
}

// ============================================================
// core packed 64x64 tile with register prefetch (software pipeline)
// ============================================================
__device__ __forceinline__ void gemm_tile(
    const uint32_t* __restrict__ Apk, int aplane, int kbtot, int kb0, int nkb,
    const uint32_t* __restrict__ Bpk, int btile_base,  // = ntile*kbtot + kb0
    int mf0, int lane, int wm, int wn, float acc[2][2][4])
{
    const uint4* aH[2];
    const uint4* aL[2];
    #pragma unroll
    for (int i = 0; i < 2; i++) {
        int mf = mf0 + wm * 2 + i;
        const uint32_t* p = Apk + ((size_t)(mf * kbtot + kb0) * 32 + lane) * 4;
        aH[i] = (const uint4*)p;
        aL[i] = (const uint4*)(p + aplane);
    }
    const uint4* bP[2];
    #pragma unroll
    for (int j = 0; j < 2; j++) {
        int nf = wn * 2 + j;
        bP[j] = (const uint4*)(Bpk + (((size_t)btile_base * 8 + nf) * 32 + lane) * 4);
    }

    uint4 ah0 = aH[0][0], al0 = aL[0][0];
    uint4 ah1 = aH[1][0], al1 = aL[1][0];
    uint4 b0  = bP[0][0], b1  = bP[1][0];

    for (int kb = 1; kb < nkb; kb++) {
        uint4 nah0 = aH[0][(size_t)kb * 32];
        uint4 nal0 = aL[0][(size_t)kb * 32];
        uint4 nah1 = aH[1][(size_t)kb * 32];
        uint4 nal1 = aL[1][(size_t)kb * 32];
        uint4 nb0  = bP[0][(size_t)kb * 256];
        uint4 nb1  = bP[1][(size_t)kb * 256];
        mma3(acc[0][0], ah0, al0, b0);
        mma3(acc[0][1], ah0, al0, b1);
        mma3(acc[1][0], ah1, al1, b0);
        mma3(acc[1][1], ah1, al1, b1);
        ah0 = nah0; al0 = nal0; ah1 = nah1; al1 = nal1; b0 = nb0; b1 = nb1;
    }
    mma3(acc[0][0], ah0, al0, b0);
    mma3(acc[0][1], ah0, al0, b1);
    mma3(acc[1][0], ah1, al1, b0);
    mma3(acc[1][1], ah1, al1, b1);
}

// ============================================================
// generic packed GEMM. grid=(ntiles, mtiles, ksplit)
// ============================================================
__global__ __launch_bounds__(256)
void gemm_pk(const uint32_t* __restrict__ Apk, int aplane, int kbtot,
             const uint32_t* __restrict__ Bpk,
             const float* __restrict__ bias, float* __restrict__ Cp,
             int nkb, int ldc, int N, long long pstride)
{
    const int tid = threadIdx.x, lane = tid & 31, warp = tid >> 5;
    const int wm = warp >> 2, wn = warp & 3;
    const int gid = lane >> 2, tig = lane & 3;
    const int ntile = blockIdx.x, mtile = blockIdx.y, z = blockIdx.z;
    const int kb0 = z * nkb;
    Cp += (long long)z * pstride;

    float acc[2][2][4] = {};
    gemm_tile(Apk, aplane, kbtot, kb0, nkb, Bpk, ntile * kbtot + kb0,
              mtile * 4, lane, wm, wn, acc);

    #pragma unroll
    for (int i = 0; i < 2; i++)
        #pragma unroll
        for (int j = 0; j < 2; j++)
            #pragma unroll
            for (int r = 0; r < 4; r++) {
                int gm = mtile * 64 + wm * 32 + i * 16 + gid + ((r >> 1) & 1) * 8;
                int gn = ntile * 64 + wn * 16 + j * 8 + tig * 2 + (r & 1);
                if (gn < N) {
                    float v = acc[i][j][r];
                    if (bias) v += bias[gn];
                    Cp[(long long)gm * ldc + gn] = v;
                }
            }
}

// ============================================================
// dec_proj GEMM for step t+1: reads h from g_hall plane t
// grid = (NT_A, 1, 1)
// ============================================================
__global__ __launch_bounds__(256)
void dec_gemm(int t, const float* __restrict__ b_dec)
{
    const int tid = threadIdx.x, lane = tid & 31, warp = tid >> 5;
    const int wm = warp >> 2, wn = warp & 3;
    const int gid = lane >> 2, tig = lane & 3;
    const int ntile = blockIdx.x;

    float acc[2][2][4] = {};
    gemm_tile(g_hall, TPLANE, KB_L, 0, KB_L, g_bpk_da,
              ntile * KB_L, t * 4, lane, wm, wn, acc);

    #pragma unroll
    for (int i = 0; i < 2; i++)
        #pragma unroll
        for (int j = 0; j < 2; j++)
            #pragma unroll
            for (int r = 0; r < 4; r++) {
                int gm = wm * 32 + i * 16 + gid + ((r >> 1) & 1) * 8;
                int gn = ntile * 64 + wn * 16 + j * 8 + tig * 2 + (r & 1);
                g_decp[gm * An + gn] = acc[i][j][r] + b_dec[gn];
            }
}

// ============================================================
// per-step logits GEMM (runs on side stream): grid=(NT_OUT,1,1)
// out[(b*Tn + t)*Vn + v] = h_t[b] @ W_out + b_out
// ============================================================
__global__ __launch_bounds__(256)
void logits_step(int t, const float* __restrict__ bias, float* __restrict__ outp)
{
    const int tid = threadIdx.x, lane = tid & 31, warp = tid >> 5;
    const int wm = warp >> 2, wn = warp & 3;
    const int gid = lane >> 2, tig = lane & 3;
    const int ntile = blockIdx.x;

    float acc[2][2][4] = {};
    gemm_tile(g_hall, TPLANE, KB_L, 0, KB_L, g_bpk_out,
              ntile * KB_L, t * 4, lane, wm, wn, acc);

    #pragma unroll
    for (int i = 0; i < 2; i++)
        #pragma unroll
        for (int j = 0; j < 2; j++)
            #pragma unroll
            for (int r = 0; r < 4; r++) {
                int b  = wm * 32 + i * 16 + gid + ((r >> 1) & 1) * 8;
                int gn = ntile * 64 + wn * 16 + j * 8 + tig * 2 + (r & 1);
                if (gn < Vn)
                    outp[((size_t)b * Tn + t) * Vn + gn] = acc[i][j][r] + bias[gn];
            }
}

// ============================================================
// mean over L of encoder_out -> g_mean (B, ENC)
// ============================================================
__global__ void mean_kernel(const float* __restrict__ enc) {
    int idx = blockIdx.x * blockDim.x + threadIdx.x;
    if (idx >= Bn * ENCn) return;
    int b = idx / ENCn, e = idx % ENCn;
    float s = 0.f;
    #pragma unroll 7
    for (int l = 0; l < Ln; l++) s += enc[(b * Ln + l) * ENCn + e];
    g_mean[idx] = s * (1.0f / (float)Ln);
}

// ============================================================
// pack A (row-major M x Kld fp32) into fragment order (hi/lo planes)
// ============================================================
__global__ void pack_A_plain(const float* __restrict__ A, uint32_t* __restrict__ out,
                             int plane, int KBtot, int Kld, int total)
{
    int id = blockIdx.x * 256 + threadIdx.x;
    if (id >= total) return;
    int lane = id & 31;
    int kb   = (id >> 5) % KBtot;
    int mf   = (id >> 5) / KBtot;
    int gid = lane >> 2, tig = lane & 3;
    long long m0 = mf * 16 + gid;
    int k0 = kb * 8 + tig;
    float v0 = A[m0 * Kld + k0];
    float v1 = A[(m0 + 8) * Kld + k0];
    float v2 = A[m0 * Kld + k0 + 4];
    float v3 = A[(m0 + 8) * Kld + k0 + 4];
    uint4 H, L;
    split_tf32(v0, H.x, L.x); split_tf32(v1, H.y, L.y);
    split_tf32(v2, H.z, L.z); split_tf32(v3, H.w, L.w);
    ((uint4*)out)[id] = H;
    ((uint4*)(out + plane))[id] = L;
}

// ============================================================
// pack B (row-major K x N fp32, ld=ldb) into fragment order
// ============================================================
__global__ void pack_B_kn(const float* __restrict__ B, uint32_t* __restrict__ out,
                          int KBtot, int N, int ldb, int total)
{
    int id = blockIdx.x * 256 + threadIdx.x;
    if (id >= total) return;
    int lane = id & 31;
    int rest = id >> 5;
    int nf = rest & 7; rest >>= 3;
    int kb = rest % KBtot;
    int ntile = rest / KBtot;
    int gid = lane >> 2, tig = lane & 3;
    int n = ntile * 64 + nf * 8 + gid;
    long long k = kb * 8 + tig;
    float v0 = (n < N) ? B[k * ldb + n] : 0.f;
    float v1 = (n < N) ? B[(k + 4) * ldb + n] : 0.f;
    uint4 W;
    split_tf32(v0, W.x, W.z);
    split_tf32(v1, W.y, W.w);
    ((uint4*)out)[id] = W;
}

// ============================================================
// pack gates B: B[k][n] = k<XKn ? W_ih[n][k] : W_hh[n][k-XKn]
// ============================================================
__global__ void pack_B_gates(const float* __restrict__ Wih, const float* __restrict__ Whh,
                             uint32_t* __restrict__ out, int total)
{
    int id = blockIdx.x * 256 + threadIdx.x;
    if (id >= total) return;
    int lane = id & 31;
    int rest = id >> 5;
    int nf = rest & 7; rest >>= 3;
    int kb = rest % KB_G;
    int ntile = rest / KB_G;
    int gid = lane >> 2, tig = lane & 3;
    long long n = ntile * 64 + nf * 8 + gid;
    int k = kb * 8 + tig;
    float v0 = (k < XKn)     ? Wih[n * XKn + k]     : Whh[n * Dn + (k - XKn)];
    float v1 = (k + 4 < XKn) ? Wih[n * XKn + k + 4] : Whh[n * Dn + (k + 4 - XKn)];
    uint4 W;
    split_tf32(v0, W.x, W.z);
    split_tf32(v1, W.y, W.w);
    ((uint4*)out)[id] = W;
}

// ============================================================
// attention (512 threads): scores, softmax, context, x-pack
// dec_proj precomputed into g_decp
// ============================================================
__global__ __launch_bounds__(512)
void attention_kernel(int t, const float* __restrict__ enc,
                      const float* __restrict__ wf,
                      const float* __restrict__ bf,
                      const int* __restrict__ captions,
                      const float* __restrict__ emb,
                      float* __restrict__ alphas_out)
{
    const int b   = blockIdx.x;
    const int tid = threadIdx.x;
    const int lane = tid & 31, wid = tid >> 5;   // 16 warps

    __shared__ float sh  [Dn];
    __shared__ float swf [An];
    __shared__ float sdec[An];
    __shared__ float ssc [Ln];
    __shared__ float sal [Ln];
    __shared__ float sctx[ENCn];

    for (int i = tid; i < Dn; i += 512) sh[i]   = g_h[b * Dn + i];
    for (int i = tid; i < An; i += 512) swf[i]  = wf[i];
    for (int i = tid; i < An; i += 512) sdec[i] = g_decp[b * An + i];
    __syncthreads();

    // scores: one warp per l
    for (int l = wid; l < Ln; l += 16) {
        const float* ep = &g_encp[(b * Ln + l) * An];
        float s = 0.f;
        #pragma unroll 4
        for (int a = lane; a < An; a += 32) {
            float v = ep[a] + sdec[a];
            v = fmaxf(v, 0.f);
            s += v * swf[a];
        }
        #pragma unroll
        for (int off = 16; off > 0; off >>= 1)
            s += __shfl_xor_sync(0xFFFFFFFFu, s, off);
        if (lane == 0) ssc[l] = s + bf[0];
    }
    __syncthreads();

    // softmax (warp 0)
    if (tid < 32) {
        float v0 = ssc[lane];
        float v1 = (lane + 32 < Ln) ? ssc[lane + 32] : -1e30f;
        float mx = fmaxf(v0, v1);
        #pragma unroll
        for (int off = 16; off > 0; off >>= 1)
            mx = fmaxf(mx, __shfl_xor_sync(0xFFFFFFFFu, mx, off));
        float e0 = expf(v0 - mx);
        float e1 = (lane + 32 < Ln) ? expf(v1 - mx) : 0.f;
        float s = e0 + e1;
        #pragma unroll
        for (int off = 16; off > 0; off >>= 1)
            s += __shfl_xor_sync(0xFFFFFFFFu, s, off);
        float inv = 1.0f / s;
        sal[lane] = e0 * inv;
        if (lane + 32 < Ln) sal[lane + 32] = e1 * inv;
    }
    __syncthreads();

    if (tid < Ln) alphas_out[(b * Tn + t) * Ln + tid] = sal[tid];

    // context
    for (int e = tid; e < ENCn; e += 512) {
        float acc = 0.f;
        #pragma unroll 7
        for (int l = 0; l < Ln; l++)
            acc += sal[l] * enc[(b * Ln + l) * ENCn + e];
        sctx[e] = acc;
    }
    __syncthreads();

    // pack x = [emb | ctx | h] row b into fragment layout
    {
        const int cap = captions[b * Tn + t];
        const int r = b & 15, mf = b >> 4;
        for (int k = tid; k < KTOT; k += 512) {
            float v = (k < En) ? emb[cap * En + k]
                    : (k < XKn) ? sctx[k - En]
                                : sh[k - XKn];
            uint32_t hi, lo; split_tf32(v, hi, lo);
            int kb = k >> 3;
            int ln2 = ((r & 7) << 2) | (k & 3);
            int w = ((r >> 3) & 1) + ((k & 4) ? 2 : 0);
            int idx = ((mf * KB_G + kb) * 32 + ln2) * 4 + w;
            g_xpk[idx] = hi;
            g_xpk[XPLANE + idx] = lo;
        }
    }
}

// ============================================================
// LSTM pointwise + pack h into this step's plane of g_hall
// ============================================================
__global__ __launch_bounds__(256)
void lstm_pointwise(int t, const float* __restrict__ b_ih, const float* __restrict__ b_hh)
{
    int idx = blockIdx.x * blockDim.x + threadIdx.x;
    if (idx >= Bn * Dn) return;
    int b = idx / Dn, d = idx % Dn;
    int base = b * 4 * Dn;

    float gi = b_ih[d]          + b_hh[d];
    float gf = b_ih[Dn + d]     + b_hh[Dn + d];
    float gg = b_ih[2 * Dn + d] + b_hh[2 * Dn + d];
    float go = b_ih[3 * Dn + d] + b_hh[3 * Dn + d];
    #pragma unroll
    for (int z = 0; z < GSPLIT; z++) {
        gi += g_gpart[z][base + d];
        gf += g_gpart[z][base + Dn + d];
        gg += g_gpart[z][base + 2 * Dn + d];
        go += g_gpart[z][base + 3 * Dn + d];
    }
    float i = 1.0f / (1.0f + expf(-gi));
    float f = 1.0f / (1.0f + expf(-gf));
    float g = tanhf(gg);
    float o = 1.0f / (1.0f + expf(-go));
    float c = f * g_c[idx] + i * g;
    g_c[idx] = c;
    float h = o * tanhf(c);
    g_h[idx] = h;

    // pack into g_hall plane for step t (mf_global = t*4 + b/16)
    uint32_t hi, lo; split_tf32(h, hi, lo);
    int r = b & 15, mfg = t * 4 + (b >> 4);
    int kb = d >> 3;
    int ln2 = ((r & 7) << 2) | (d & 3);
    int w = ((r >> 3) & 1) + ((d & 4) ? 2 : 0);
    int j = ((mfg * KB_L + kb) * 32 + ln2) * 4 + w;
    g_hall[j] = hi;
    g_hall[TPLANE + j] = lo;
}

// ============================================================
// launch
// ============================================================
extern "C" void kernel_launch(void* const* d_in, const int* in_sizes, int n_in,
                              void* d_out, int out_size)
{
    const float* enc       = (const float*)d_in[0];
    const int*   captions  = (const int*)  d_in[1];
    const float* emb       = (const float*)d_in[2];
    const float* W_enc_att = (const float*)d_in[3];
    const float* b_enc_att = (const float*)d_in[4];
    const float* W_dec_att = (const float*)d_in[5];
    const float* b_dec_att = (const float*)d_in[6];
    const float* w_full    = (const float*)d_in[7];
    const float* b_full    = (const float*)d_in[8];
    const float* W_ih      = (const float*)d_in[9];
    const float* b_ih      = (const float*)d_in[10];
    const float* W_hh      = (const float*)d_in[11];
    const float* b_hh      = (const float*)d_in[12];
    const float* W_init_h  = (const float*)d_in[13];
    const float* b_init_h  = (const float*)d_in[14];
    const float* W_init_c  = (const float*)d_in[15];
    const float* b_init_c  = (const float*)d_in[16];
    const float* W_out     = (const float*)d_in[17];
    const float* b_out     = (const float*)d_in[18];

    float* out        = (float*)d_out;
    float* alphas_out = out + (size_t)Bn * Tn * Vn;

    // side stream + events for concurrent logits (host resources, created once)
    static cudaStream_t s_side = nullptr;
    static cudaEvent_t  s_ev[Tn];
    static cudaEvent_t  s_join = nullptr;
    if (!s_side) {
        cudaStreamCreateWithFlags(&s_side, cudaStreamNonBlocking);
        for (int t = 0; t < Tn; t++)
            cudaEventCreateWithFlags(&s_ev[t], cudaEventDisableTiming);
        cudaEventCreateWithFlags(&s_join, cudaEventDisableTiming);
    }

    float *p_mean, *p_h, *p_c, *p_encp, *p_gpart, *p_decp;
    uint32_t *p_xpk, *p_hpk, *p_apk_enc, *p_apk_mean;
    uint32_t *p_bout, *p_bg, *p_bea, *p_bih, *p_bic, *p_bda;
    cudaGetSymbolAddress((void**)&p_mean,     g_mean);
    cudaGetSymbolAddress((void**)&p_h,        g_h);
    cudaGetSymbolAddress((void**)&p_c,        g_c);
    cudaGetSymbolAddress((void**)&p_encp,     g_encp);
    cudaGetSymbolAddress((void**)&p_decp,     g_decp);
    cudaGetSymbolAddress((void**)&p_gpart,    g_gpart);
    cudaGetSymbolAddress((void**)&p_xpk,      g_xpk);
    cudaGetSymbolAddress((void**)&p_hpk,      g_hpk);
    cudaGetSymbolAddress((void**)&p_apk_enc,  g_apk_enc);
    cudaGetSymbolAddress((void**)&p_apk_mean, g_apk_mean);
    cudaGetSymbolAddress((void**)&p_bout,     g_bpk_out);
    cudaGetSymbolAddress((void**)&p_bg,       g_bpk_g);
    cudaGetSymbolAddress((void**)&p_bea,      g_bpk_ea);
    cudaGetSymbolAddress((void**)&p_bih,      g_bpk_ih);
    cudaGetSymbolAddress((void**)&p_bic,      g_bpk_ic);
    cudaGetSymbolAddress((void**)&p_bda,      g_bpk_da);

    // ---- weight packs ----
    {
        int tot = NT_OUT * KB_L * 8 * 32;
        pack_B_kn<<<(tot + 255) / 256, 256>>>(W_out, p_bout, KB_L, Vn, Vn, tot);
    }
    {
        int tot = NT_G * KB_G * 8 * 32;
        pack_B_gates<<<(tot + 255) / 256, 256>>>(W_ih, W_hh, p_bg, tot);
    }
    {
        int tot = NT_A * KB_E * 8 * 32;
        pack_B_kn<<<(tot + 255) / 256, 256>>>(W_enc_att, p_bea, KB_E, An, An, tot);
        pack_B_kn<<<(tot + 255) / 256, 256>>>(W_init_h,  p_bih, KB_E, Dn, Dn, tot);
        pack_B_kn<<<(tot + 255) / 256, 256>>>(W_init_c,  p_bic, KB_E, Dn, Dn, tot);
    }
    {
        int tot = NT_A * KB_L * 8 * 32;
        pack_B_kn<<<(tot + 255) / 256, 256>>>(W_dec_att, p_bda, KB_L, An, An, tot);
    }

    // ---- init ----
    mean_kernel<<<(Bn * ENCn + 255) / 256, 256>>>(enc);
    {
        int tot = 4 * KB_E * 32;
        pack_A_plain<<<(tot + 255) / 256, 256>>>(p_mean, p_apk_mean, MPLANE, KB_E, ENCn, tot);
    }
    gemm_pk<<<dim3(NT_A, 1, 1), 256>>>(p_apk_mean, MPLANE, KB_E, p_bih,
                                       b_init_h, p_h, KB_E, Dn, Dn, 0);
    gemm_pk<<<dim3(NT_A, 1, 1), 256>>>(p_apk_mean, MPLANE, KB_E, p_bic,
                                       b_init_c, p_c, KB_E, Dn, Dn, 0);
    {
        int tot = MF_ENC * KB_E * 32;
        pack_A_plain<<<(tot + 255) / 256, 256>>>(enc, p_apk_enc, EPLANE, KB_E, ENCn, tot);
    }
    gemm_pk<<<dim3(NT_A, Bn * Ln / 64, 1), 256>>>(p_apk_enc, EPLANE, KB_E, p_bea,
                                                  b_enc_att, p_encp, KB_E, An, An, 0);
    // pack h_init and compute initial dec_proj
    {
        int tot = 4 * KB_L * 32;
        pack_A_plain<<<(tot + 255) / 256, 256>>>(p_h, p_hpk, HPLANE, KB_L, Dn, tot);
    }
    gemm_pk<<<dim3(NT_A, 1, 1), 256>>>(p_hpk, HPLANE, KB_L, p_bda,
                                       b_dec_att, p_decp, KB_L, An, An, 0);

    // ---- time steps; logits_t runs concurrently on the side stream ----
    for (int t = 0; t < Tn; t++) {
        attention_kernel<<<Bn, 512>>>(t, enc, w_full, b_full,
                                      captions, emb, alphas_out);
        gemm_pk<<<dim3(NT_G, 1, GSPLIT), 256>>>(p_xpk, XPLANE, KB_G, p_bg,
                                                nullptr, p_gpart,
                                                NKB_G, 4 * Dn, 4 * Dn,
                                                (long long)Bn * 4 * Dn);
        lstm_pointwise<<<(Bn * Dn + 255) / 256, 256>>>(t, b_ih, b_hh);

        // fork: logits_t depends only on lstm_t; run it off the critical stream
        cudaEventRecord(s_ev[t], 0);
        cudaStreamWaitEvent(s_side, s_ev[t], 0);
        logits_step<<<NT_OUT, 256, 0, s_side>>>(t, b_out, out);

        if (t + 1 < Tn)
            dec_gemm<<<NT_A, 256>>>(t, b_dec_att);
    }

    // join side stream back before capture ends
    cudaEventRecord(s_join, s_side);
    cudaStreamWaitEvent(0, s_join, 0);
}